// round 1
// baseline (speedup 1.0000x reference)
#include <cuda_runtime.h>
#include <math.h>
#include <float.h>

// Problem dims
#define B_ 2
#define S_ 2048
#define H_ 16
#define D_ 128
#define E_ 2048
#define M_ (B_*S_)   // 4096 tokens

// Scratch (device globals: allocation-free, graph-capturable)
__device__ float g_Q[B_*H_*S_*D_];   // 32 MB
__device__ float g_K[B_*H_*S_*D_];   // 32 MB
__device__ float g_V[B_*H_*S_*D_];   // 32 MB
__device__ float g_A[M_*E_];         // 32 MB  attention output in [B,S,H*D]

// ---------------------------------------------------------------------------
// Kernel 1: QKV projection. C[m,f] = sum_e X[m,e] * W[f,e]  (NT gemm)
// Epilogue writes to [B,H,S,D] layout. blockIdx.z selects Q/K/V.
// Tiles: BM=64, BN=64, BK=16, 256 threads, 4x4 register micro-tile.
// ---------------------------------------------------------------------------
__global__ __launch_bounds__(256) void qkv_kernel(
    const float* __restrict__ X,
    const float* __restrict__ Wq,
    const float* __restrict__ Wk,
    const float* __restrict__ Wv)
{
    const float* W   = (blockIdx.z == 0) ? Wq : (blockIdx.z == 1) ? Wk : Wv;
    float*       Out = (blockIdx.z == 0) ? g_Q : (blockIdx.z == 1) ? g_K : g_V;

    __shared__ __align__(16) float As[16][64];
    __shared__ __align__(16) float Bs[16][64];

    const int tid = threadIdx.x;
    const int tx  = tid & 15;       // 0..15 -> n micro
    const int ty  = tid >> 4;       // 0..15 -> m micro
    const int m0  = blockIdx.y * 64;
    const int n0  = blockIdx.x * 64;

    const int lr = tid >> 2;          // 0..63 row within tile
    const int lc = (tid & 3) << 2;    // 0,4,8,12 col within k-slab

    const float* Aptr = X + (size_t)(m0 + lr) * E_ + lc;
    const float* Bptr = W + (size_t)(n0 + lr) * E_ + lc;

    float acc[4][4] = {};

    for (int k0 = 0; k0 < E_; k0 += 16) {
        float4 a = *(const float4*)(Aptr + k0);
        float4 b = *(const float4*)(Bptr + k0);
        As[lc + 0][lr] = a.x; As[lc + 1][lr] = a.y;
        As[lc + 2][lr] = a.z; As[lc + 3][lr] = a.w;
        Bs[lc + 0][lr] = b.x; Bs[lc + 1][lr] = b.y;
        Bs[lc + 2][lr] = b.z; Bs[lc + 3][lr] = b.w;
        __syncthreads();
#pragma unroll
        for (int k = 0; k < 16; k++) {
            float4 ra = *(const float4*)&As[k][ty << 2];
            float4 rb = *(const float4*)&Bs[k][tx << 2];
            float av[4] = {ra.x, ra.y, ra.z, ra.w};
            float bv[4] = {rb.x, rb.y, rb.z, rb.w};
#pragma unroll
            for (int i = 0; i < 4; i++)
#pragma unroll
                for (int j = 0; j < 4; j++)
                    acc[i][j] = fmaf(av[i], bv[j], acc[i][j]);
        }
        __syncthreads();
    }

    // Epilogue -> [B,H,S,D]
    const int f = n0 + (tx << 2);     // 4 consecutive f, within one head (f%4==0, D=128)
    const int h = f >> 7;
    const int d = f & 127;
#pragma unroll
    for (int i = 0; i < 4; i++) {
        int m = m0 + (ty << 2) + i;
        int b = m >> 11;              // /S_
        int s = m & (S_ - 1);
        float4 o = make_float4(acc[i][0], acc[i][1], acc[i][2], acc[i][3]);
        *(float4*)&Out[(((size_t)(b * H_ + h)) * S_ + s) * D_ + d] = o;
    }
}

// ---------------------------------------------------------------------------
// Kernel 2: RoPE on g_Q, g_K in-place. block = (s,h,b), 128 threads (=D).
// ---------------------------------------------------------------------------
__global__ void rope_kernel(const int* __restrict__ pos_ids)
{
    const int d = threadIdx.x;     // 0..127
    const int s = blockIdx.x;
    const int h = blockIdx.y;
    const int b = blockIdx.z;

    const size_t base = (((size_t)(b * H_ + h)) * S_ + s) * D_;
    const float pos = (float)pos_ids[b * S_ + s];
    const int i = d & 63;
    // inv_freq = theta^{-2i/D}
    const float inv = powf(10000.0f, -(float)(2 * i) / (float)D_);
    const float ang = pos * inv;
    float sn, cs;
    sincosf(ang, &sn, &cs);

    float q  = g_Q[base + d];
    float qr = (d < 64) ? -g_Q[base + d + 64] : g_Q[base + d - 64];
    float k  = g_K[base + d];
    float kr = (d < 64) ? -g_K[base + d + 64] : g_K[base + d - 64];
    __syncthreads();   // all partner reads complete before any write
    g_Q[base + d] = q * cs + qr * sn;
    g_K[base + d] = k * cs + kr * sn;
}

// ---------------------------------------------------------------------------
// Kernel 3: causal flash attention.
// block = (q_tile, h, b); 256 threads. BQ=BK=64, D=128.
// smem: Qs[128][68], Ks[128][68] (d-major), Vs[64][128], Ps[64][68].
// ---------------------------------------------------------------------------
#define QS_STRIDE 68
#define ATTN_SMEM_FLOATS (128*QS_STRIDE + 128*QS_STRIDE + 64*128 + 64*QS_STRIDE)
#define ATTN_SMEM_BYTES  (ATTN_SMEM_FLOATS * 4)

__global__ __launch_bounds__(256) void attn_kernel()
{
    const int qt = blockIdx.x;     // 0..31
    const int h  = blockIdx.y;
    const int b  = blockIdx.z;

    const float* Qg = g_Q + (((size_t)(b * H_ + h)) * S_) * D_;
    const float* Kg = g_K + (((size_t)(b * H_ + h)) * S_) * D_;
    const float* Vg = g_V + (((size_t)(b * H_ + h)) * S_) * D_;

    extern __shared__ float sm[];
    float* Qs = sm;                        // [128][68] d-major
    float* Ks = Qs + 128 * QS_STRIDE;      // [128][68] d-major
    float* Vs = Ks + 128 * QS_STRIDE;      // [64][128] k-major
    float* Ps = Vs + 64 * 128;             // [64][68]  Ps[k][q]

    const int tid = threadIdx.x;
    const int tx  = tid & 15;   // key / dcol group
    const int ty  = tid >> 4;   // query group (4 rows)

    // Load Q tile transposed: Qs[d][q]
#pragma unroll
    for (int it = 0; it < 8; it++) {
        int lin = it * 256 + tid;      // 0..2047
        int q   = lin >> 5;            // 0..63
        int c4  = (lin & 31) << 2;     // 0..124 step 4
        float4 v = *(const float4*)&Qg[(size_t)(qt * 64 + q) * D_ + c4];
        Qs[(c4 + 0) * QS_STRIDE + q] = v.x;
        Qs[(c4 + 1) * QS_STRIDE + q] = v.y;
        Qs[(c4 + 2) * QS_STRIDE + q] = v.z;
        Qs[(c4 + 3) * QS_STRIDE + q] = v.w;
    }

    float m_[4], l_[4], o_[4][8];
#pragma unroll
    for (int i = 0; i < 4; i++) {
        m_[i] = -INFINITY; l_[i] = 0.f;
#pragma unroll
        for (int j = 0; j < 8; j++) o_[i][j] = 0.f;
    }
    const float scale = 0.088388347648318447f;  // 1/sqrt(128)

    for (int kt = 0; kt <= qt; kt++) {
        __syncthreads();   // prior iter done with Ks/Vs/Ps; also orders Q fill (iter 0)
        // Load K tile transposed + V tile direct
#pragma unroll
        for (int it = 0; it < 8; it++) {
            int lin = it * 256 + tid;
            int r   = lin >> 5;
            int c4  = (lin & 31) << 2;
            float4 kv = *(const float4*)&Kg[(size_t)(kt * 64 + r) * D_ + c4];
            Ks[(c4 + 0) * QS_STRIDE + r] = kv.x;
            Ks[(c4 + 1) * QS_STRIDE + r] = kv.y;
            Ks[(c4 + 2) * QS_STRIDE + r] = kv.z;
            Ks[(c4 + 3) * QS_STRIDE + r] = kv.w;
            float4 vv = *(const float4*)&Vg[(size_t)(kt * 64 + r) * D_ + c4];
            *(float4*)&Vs[r * 128 + c4] = vv;
        }
        __syncthreads();

        // S = Q K^T  (4q x 4k per thread)
        float s4[4][4] = {};
#pragma unroll 8
        for (int d = 0; d < 128; d++) {
            float4 ra = *(const float4*)&Qs[d * QS_STRIDE + (ty << 2)];
            float4 rb = *(const float4*)&Ks[d * QS_STRIDE + (tx << 2)];
            float av[4] = {ra.x, ra.y, ra.z, ra.w};
            float bv[4] = {rb.x, rb.y, rb.z, rb.w};
#pragma unroll
            for (int i = 0; i < 4; i++)
#pragma unroll
                for (int j = 0; j < 4; j++)
                    s4[i][j] = fmaf(av[i], bv[j], s4[i][j]);
        }

        const bool diag = (kt == qt);
#pragma unroll
        for (int i = 0; i < 4; i++) {
            int qq = (ty << 2) + i;
#pragma unroll
            for (int j = 0; j < 4; j++) {
                s4[i][j] *= scale;
                if (diag && ((tx << 2) + j) > qq) s4[i][j] = -INFINITY;
            }
        }

        // online softmax per q row; reduce across the 16 tx threads
#pragma unroll
        for (int i = 0; i < 4; i++) {
            float mx = fmaxf(fmaxf(s4[i][0], s4[i][1]), fmaxf(s4[i][2], s4[i][3]));
#pragma unroll
            for (int off = 1; off < 16; off <<= 1)
                mx = fmaxf(mx, __shfl_xor_sync(0xffffffffu, mx, off));
            float mn = fmaxf(m_[i], mx);
            float corr = expf(m_[i] - mn);
            m_[i] = mn;
            float rs = 0.f;
#pragma unroll
            for (int j = 0; j < 4; j++) {
                float p = expf(s4[i][j] - mn);
                s4[i][j] = p;
                rs += p;
            }
#pragma unroll
            for (int off = 1; off < 16; off <<= 1)
                rs += __shfl_xor_sync(0xffffffffu, rs, off);
            l_[i] = l_[i] * corr + rs;
#pragma unroll
            for (int jd = 0; jd < 8; jd++) o_[i][jd] *= corr;
            // stage P transposed: Ps[k][q]
#pragma unroll
            for (int j = 0; j < 4; j++)
                Ps[((tx << 2) + j) * QS_STRIDE + (ty << 2) + i] = s4[i][j];
        }
        __syncthreads();

        // O += P @ V   (4q x 8d per thread)
#pragma unroll 4
        for (int kk = 0; kk < 64; kk++) {
            float4 p4 = *(const float4*)&Ps[kk * QS_STRIDE + (ty << 2)];
            float4 v0 = *(const float4*)&Vs[kk * 128 + (tx << 3)];
            float4 v1 = *(const float4*)&Vs[kk * 128 + (tx << 3) + 4];
            float pv[4] = {p4.x, p4.y, p4.z, p4.w};
            float vv[8] = {v0.x, v0.y, v0.z, v0.w, v1.x, v1.y, v1.z, v1.w};
#pragma unroll
            for (int i = 0; i < 4; i++)
#pragma unroll
                for (int jd = 0; jd < 8; jd++)
                    o_[i][jd] = fmaf(pv[i], vv[jd], o_[i][jd]);
        }
    }

    // epilogue: normalize and write to g_A in [B,S,H*D]
#pragma unroll
    for (int i = 0; i < 4; i++) {
        float invl = 1.f / l_[i];
        int q = qt * 64 + (ty << 2) + i;
        float* dst = g_A + ((size_t)(b * S_ + q)) * E_ + h * D_ + (tx << 3);
        float4 out0 = make_float4(o_[i][0] * invl, o_[i][1] * invl,
                                  o_[i][2] * invl, o_[i][3] * invl);
        float4 out1 = make_float4(o_[i][4] * invl, o_[i][5] * invl,
                                  o_[i][6] * invl, o_[i][7] * invl);
        *(float4*)dst       = out0;
        *(float4*)(dst + 4) = out1;
    }
}

// ---------------------------------------------------------------------------
// Kernel 4: output projection. out[m,e] = sum_f A[m,f] * Wo[e,f]
// ---------------------------------------------------------------------------
__global__ __launch_bounds__(256) void oproj_kernel(
    const float* __restrict__ Wo, float* __restrict__ out)
{
    __shared__ __align__(16) float As[16][64];
    __shared__ __align__(16) float Bs[16][64];

    const int tid = threadIdx.x;
    const int tx  = tid & 15;
    const int ty  = tid >> 4;
    const int m0  = blockIdx.y * 64;
    const int n0  = blockIdx.x * 64;

    const int lr = tid >> 2;
    const int lc = (tid & 3) << 2;

    const float* Aptr = g_A + (size_t)(m0 + lr) * E_ + lc;
    const float* Bptr = Wo  + (size_t)(n0 + lr) * E_ + lc;

    float acc[4][4] = {};

    for (int k0 = 0; k0 < E_; k0 += 16) {
        float4 a = *(const float4*)(Aptr + k0);
        float4 b = *(const float4*)(Bptr + k0);
        As[lc + 0][lr] = a.x; As[lc + 1][lr] = a.y;
        As[lc + 2][lr] = a.z; As[lc + 3][lr] = a.w;
        Bs[lc + 0][lr] = b.x; Bs[lc + 1][lr] = b.y;
        Bs[lc + 2][lr] = b.z; Bs[lc + 3][lr] = b.w;
        __syncthreads();
#pragma unroll
        for (int k = 0; k < 16; k++) {
            float4 ra = *(const float4*)&As[k][ty << 2];
            float4 rb = *(const float4*)&Bs[k][tx << 2];
            float av[4] = {ra.x, ra.y, ra.z, ra.w};
            float bv[4] = {rb.x, rb.y, rb.z, rb.w};
#pragma unroll
            for (int i = 0; i < 4; i++)
#pragma unroll
                for (int j = 0; j < 4; j++)
                    acc[i][j] = fmaf(av[i], bv[j], acc[i][j]);
        }
        __syncthreads();
    }

#pragma unroll
    for (int i = 0; i < 4; i++) {
        int m = m0 + (ty << 2) + i;
        float4 o = make_float4(acc[i][0], acc[i][1], acc[i][2], acc[i][3]);
        *(float4*)&out[(size_t)m * E_ + n0 + (tx << 2)] = o;
    }
}

// ---------------------------------------------------------------------------
extern "C" void kernel_launch(void* const* d_in, const int* in_sizes, int n_in,
                              void* d_out, int out_size)
{
    const float* hidden = (const float*)d_in[0];
    // d_in[1] = attention_mask (causal additive; applied analytically)
    const int*   posids = (const int*)d_in[2];
    const float* Wq     = (const float*)d_in[3];
    const float* Wk     = (const float*)d_in[4];
    const float* Wv     = (const float*)d_in[5];
    const float* Wo     = (const float*)d_in[6];
    float*       out    = (float*)d_out;

    cudaFuncSetAttribute(attn_kernel,
                         cudaFuncAttributeMaxDynamicSharedMemorySize,
                         ATTN_SMEM_BYTES);

    // 1) QKV projections -> [B,H,S,D]
    {
        dim3 grid(E_ / 64, M_ / 64, 3);
        qkv_kernel<<<grid, 256>>>(hidden, Wq, Wk, Wv);
    }
    // 2) RoPE in place
    {
        dim3 grid(S_, H_, B_);
        rope_kernel<<<grid, 128>>>(posids);
    }
    // 3) causal flash attention -> g_A [B,S,H*D]
    {
        dim3 grid(S_ / 64, H_, B_);
        attn_kernel<<<grid, 256, ATTN_SMEM_BYTES>>>();
    }
    // 4) output projection -> d_out
    {
        dim3 grid(E_ / 64, M_ / 64);
        oproj_kernel<<<grid, 256>>>(Wo, out);
    }
}

// round 3
// speedup vs baseline: 2.0742x; 2.0742x over previous
#include <cuda_runtime.h>
#include <cuda_bf16.h>
#include <math.h>
#include <float.h>
#include <stdint.h>

// Problem dims
#define B_ 2
#define S_ 2048
#define H_ 16
#define D_ 128
#define E_ 2048
#define M_ (B_*S_)   // 4096 tokens

// Scratch (device globals: allocation-free, graph-capturable)
__device__ float g_Q[B_*H_*S_*D_];   // 32 MB
__device__ float g_K[B_*H_*S_*D_];   // 32 MB
__device__ float g_V[B_*H_*S_*D_];   // 32 MB
__device__ float g_A[M_*E_];         // 32 MB  attention output in [B,S,H*D]

// bf16 hi/lo splits
__device__ __nv_bfloat16 g_Xh[M_*E_];       // 16 MB
__device__ __nv_bfloat16 g_Xl[M_*E_];
__device__ __nv_bfloat16 g_Wh[4*E_*E_];     // 32 MB  (q,k,v,o)
__device__ __nv_bfloat16 g_Wl[4*E_*E_];
__device__ __nv_bfloat16 g_Ah[M_*E_];
__device__ __nv_bfloat16 g_Al[M_*E_];

__device__ __forceinline__ uint32_t smem_to_u32(const void* smem_ptr) {
    uint32_t addr;
    asm("{ .reg .u64 tmp; cvta.to.shared.u64 tmp, %1; cvt.u32.u64 %0, tmp; }"
        : "=r"(addr) : "l"(smem_ptr));
    return addr;
}

#define CP_ASYNC16(dst, src) \
    asm volatile("cp.async.cg.shared.global [%0], [%1], 16;" \
        :: "r"(dst), "l"(src) : "memory")
#define CP_ASYNC_COMMIT() asm volatile("cp.async.commit_group;" ::: "memory")
#define CP_ASYNC_WAIT0()  asm volatile("cp.async.wait_group 0;" ::: "memory")

__device__ __forceinline__ void ldsm_x4(uint32_t* r, uint32_t addr) {
    asm volatile("ldmatrix.sync.aligned.m8n8.x4.shared.b16 {%0,%1,%2,%3}, [%4];"
        : "=r"(r[0]), "=r"(r[1]), "=r"(r[2]), "=r"(r[3]) : "r"(addr));
}

__device__ __forceinline__ void mma16816(float* c, const uint32_t* a,
                                          uint32_t b0, uint32_t b1) {
    asm volatile(
        "mma.sync.aligned.m16n8k16.row.col.f32.bf16.bf16.f32 "
        "{%0,%1,%2,%3}, {%4,%5,%6,%7}, {%8,%9}, {%0,%1,%2,%3};"
        : "+f"(c[0]), "+f"(c[1]), "+f"(c[2]), "+f"(c[3])
        : "r"(a[0]), "r"(a[1]), "r"(a[2]), "r"(a[3]), "r"(b0), "r"(b1));
}

// ---------------------------------------------------------------------------
// Split fp32 -> bf16 hi + bf16 lo
// ---------------------------------------------------------------------------
__global__ __launch_bounds__(256) void split_kernel(
    const float* __restrict__ src,
    __nv_bfloat16* __restrict__ hi,
    __nv_bfloat16* __restrict__ lo,
    int n4)
{
    int idx = blockIdx.x * blockDim.x + threadIdx.x;
    if (idx >= n4) return;
    float4 v = ((const float4*)src)[idx];
    __nv_bfloat16 h0 = __float2bfloat16(v.x);
    __nv_bfloat16 h1 = __float2bfloat16(v.y);
    __nv_bfloat16 h2 = __float2bfloat16(v.z);
    __nv_bfloat16 h3 = __float2bfloat16(v.w);
    __nv_bfloat16 l0 = __float2bfloat16(v.x - __bfloat162float(h0));
    __nv_bfloat16 l1 = __float2bfloat16(v.y - __bfloat162float(h1));
    __nv_bfloat16 l2 = __float2bfloat16(v.z - __bfloat162float(h2));
    __nv_bfloat16 l3 = __float2bfloat16(v.w - __bfloat162float(h3));
    __nv_bfloat162 hp0 = __halves2bfloat162(h0, h1);
    __nv_bfloat162 hp1 = __halves2bfloat162(h2, h3);
    __nv_bfloat162 lp0 = __halves2bfloat162(l0, l1);
    __nv_bfloat162 lp1 = __halves2bfloat162(l2, l3);
    uint2 hw, lw;
    hw.x = *(uint32_t*)&hp0; hw.y = *(uint32_t*)&hp1;
    lw.x = *(uint32_t*)&lp0; lw.y = *(uint32_t*)&lp1;
    ((uint2*)hi)[idx] = hw;
    ((uint2*)lo)[idx] = lw;
}

// ---------------------------------------------------------------------------
// mma.sync bf16 (3-term split) GEMM: C[m,n] = sum_k A[m,k] * W[n,k]
// Block tile 128x128, 8 warps (warp tile 32x64), K-chunk 32, double-buffered.
// MODE 0: qkv (z selects W slot 0..2, writes g_Q/g_K/g_V in [B,H,S,D])
// MODE 1: oproj (A = g_A split, W slot 3, writes Oout [M][E])
// ---------------------------------------------------------------------------
#define KCH 32
#define NKC (E_/KCH)          // 64
#define ROWB 80               // bytes per smem row (32 bf16 + pad 8)
#define TILE_B (128*ROWB)     // 10240
#define STG_B  (4*TILE_B)     // 40960
#define GEMM_SMEM (2*STG_B)   // 81920

template<int MODE>
__global__ __launch_bounds__(256, 1) void gemm_mma(float* __restrict__ Oout)
{
    extern __shared__ char gsm[];
    const uint32_t sb = smem_to_u32(gsm);

    const int tid  = threadIdx.x;
    const int lane = tid & 31;
    const int wid  = tid >> 5;
    const int warpM = wid & 3;     // 4 -> 128 rows
    const int warpN = wid >> 2;    // 2 -> 128 cols
    const int m0 = blockIdx.y * 128;
    const int n0 = blockIdx.x * 128;
    const int z  = (MODE == 0) ? blockIdx.z : 3;

    const __nv_bfloat16* Ahg = (MODE == 0) ? g_Xh : g_Ah;
    const __nv_bfloat16* Alg = (MODE == 0) ? g_Xl : g_Al;
    const __nv_bfloat16* Bhg = g_Wh + (size_t)z * E_ * E_;
    const __nv_bfloat16* Blg = g_Wl + (size_t)z * E_ * E_;

    // per-thread cp.async mapping: chunks tid and tid+256 per tile
    const int r0c = tid >> 2, p0 = tid & 3;           // row 0..63
    const int r1c = r0c + 64, p1 = p0;

    float c[2][8][4];
#pragma unroll
    for (int i = 0; i < 2; i++)
#pragma unroll
        for (int j = 0; j < 8; j++)
#pragma unroll
            for (int q = 0; q < 4; q++) c[i][j][q] = 0.f;

    // ldmatrix base addresses (per thread), byte offsets within a stage
    // A: row = warpM*32 + mi*16 + (lane&15); colhalf = lane>>4
    const uint32_t aRow = (uint32_t)(warpM * 32 + (lane & 15)) * ROWB + (uint32_t)(lane >> 4) * 16;
    // B: row = warpN*64 + g*16 + (lane&7) + ((lane>>4)<<3); colhalf = (lane>>3)&1
    const uint32_t bRow = (uint32_t)(warpN * 64 + (lane & 7) + ((lane >> 4) << 3)) * ROWB
                        + (uint32_t)((lane >> 3) & 1) * 16;

    auto load_stage = [&](int buf, int kc) {
        const uint32_t stg = sb + buf * STG_B;
        const size_t gA0 = (size_t)(m0 + r0c) * E_ + kc * KCH + p0 * 8;
        const size_t gA1 = (size_t)(m0 + r1c) * E_ + kc * KCH + p1 * 8;
        const size_t gB0 = (size_t)(n0 + r0c) * E_ + kc * KCH + p0 * 8;
        const size_t gB1 = (size_t)(n0 + r1c) * E_ + kc * KCH + p1 * 8;
        const uint32_t s0 = (uint32_t)(r0c * ROWB + p0 * 16);
        const uint32_t s1 = (uint32_t)(r1c * ROWB + p1 * 16);
        CP_ASYNC16(stg + 0 * TILE_B + s0, Ahg + gA0);
        CP_ASYNC16(stg + 0 * TILE_B + s1, Ahg + gA1);
        CP_ASYNC16(stg + 1 * TILE_B + s0, Alg + gA0);
        CP_ASYNC16(stg + 1 * TILE_B + s1, Alg + gA1);
        CP_ASYNC16(stg + 2 * TILE_B + s0, Bhg + gB0);
        CP_ASYNC16(stg + 2 * TILE_B + s1, Bhg + gB1);
        CP_ASYNC16(stg + 3 * TILE_B + s0, Blg + gB0);
        CP_ASYNC16(stg + 3 * TILE_B + s1, Blg + gB1);
        CP_ASYNC_COMMIT();
    };

    load_stage(0, 0);

    for (int kc = 0; kc < NKC; kc++) {
        const int buf = kc & 1;
        CP_ASYNC_WAIT0();
        __syncthreads();
        if (kc + 1 < NKC) load_stage(buf ^ 1, kc + 1);

        const uint32_t stg = sb + buf * STG_B;
#pragma unroll
        for (int ks = 0; ks < 2; ks++) {
            uint32_t ah[2][4], al[2][4], bh[4][4], bl[4][4];
#pragma unroll
            for (int mi = 0; mi < 2; mi++) {
                uint32_t aoff = stg + aRow + (uint32_t)mi * 16 * ROWB + (uint32_t)ks * 32;
                ldsm_x4(ah[mi], aoff + 0 * TILE_B);
                ldsm_x4(al[mi], aoff + 1 * TILE_B);
            }
#pragma unroll
            for (int g = 0; g < 4; g++) {
                uint32_t boff = stg + bRow + (uint32_t)g * 16 * ROWB + (uint32_t)ks * 32;
                ldsm_x4(bh[g], boff + 2 * TILE_B);
                ldsm_x4(bl[g], boff + 3 * TILE_B);
            }
#pragma unroll
            for (int mi = 0; mi < 2; mi++) {
#pragma unroll
                for (int g = 0; g < 4; g++) {
#pragma unroll
                    for (int hh = 0; hh < 2; hh++) {
                        float* cc = c[mi][2 * g + hh];
                        mma16816(cc, ah[mi], bh[g][2 * hh], bh[g][2 * hh + 1]);
                        mma16816(cc, ah[mi], bl[g][2 * hh], bl[g][2 * hh + 1]);
                        mma16816(cc, al[mi], bh[g][2 * hh], bh[g][2 * hh + 1]);
                    }
                }
            }
        }
        __syncthreads();
    }

    // Epilogue. Thread holds (row g, col 2t) and (row g+8, col 2t) per atom.
    const int rr = lane >> 2;
    const int ct = 2 * (lane & 3);
#pragma unroll
    for (int mi = 0; mi < 2; mi++) {
#pragma unroll
        for (int ni = 0; ni < 8; ni++) {
            int row = m0 + warpM * 32 + mi * 16 + rr;
            int col = n0 + warpN * 64 + ni * 8 + ct;
            if (MODE == 0) {
                float* Out = (z == 0) ? g_Q : (z == 1) ? g_K : g_V;
                const int h = col >> 7;
                const int d = col & 127;
                int bb = row >> 11, ss = row & (S_ - 1);
                size_t base0 = (((size_t)(bb * H_ + h)) * S_ + ss) * D_ + d;
                *(float2*)&Out[base0] = make_float2(c[mi][ni][0], c[mi][ni][1]);
                int row2 = row + 8;
                bb = row2 >> 11; ss = row2 & (S_ - 1);
                size_t base1 = (((size_t)(bb * H_ + h)) * S_ + ss) * D_ + d;
                *(float2*)&Out[base1] = make_float2(c[mi][ni][2], c[mi][ni][3]);
            } else {
                *(float2*)&Oout[(size_t)row * E_ + col] =
                    make_float2(c[mi][ni][0], c[mi][ni][1]);
                *(float2*)&Oout[(size_t)(row + 8) * E_ + col] =
                    make_float2(c[mi][ni][2], c[mi][ni][3]);
            }
        }
    }
}

// ---------------------------------------------------------------------------
// RoPE on g_Q, g_K in-place. block = (s,h,b), 128 threads (=D).
// ---------------------------------------------------------------------------
__global__ void rope_kernel(const int* __restrict__ pos_ids)
{
    const int d = threadIdx.x;
    const int s = blockIdx.x;
    const int h = blockIdx.y;
    const int b = blockIdx.z;

    const size_t base = (((size_t)(b * H_ + h)) * S_ + s) * D_;
    const float pos = (float)pos_ids[b * S_ + s];
    const int i = d & 63;
    const float inv = powf(10000.0f, -(float)(2 * i) / (float)D_);
    const float ang = pos * inv;
    float sn, cs;
    sincosf(ang, &sn, &cs);

    float q  = g_Q[base + d];
    float qr = (d < 64) ? -g_Q[base + d + 64] : g_Q[base + d - 64];
    float k  = g_K[base + d];
    float kr = (d < 64) ? -g_K[base + d + 64] : g_K[base + d - 64];
    __syncthreads();
    g_Q[base + d] = q * cs + qr * sn;
    g_K[base + d] = k * cs + kr * sn;
}

// ---------------------------------------------------------------------------
// Causal flash attention (fp32 FFMA). block = (q_tile, h, b); 256 threads.
// ---------------------------------------------------------------------------
#define QS_STRIDE 68
#define ATTN_SMEM_FLOATS (128*QS_STRIDE + 128*QS_STRIDE + 64*128 + 64*QS_STRIDE)
#define ATTN_SMEM_BYTES  (ATTN_SMEM_FLOATS * 4)

__global__ __launch_bounds__(256) void attn_kernel()
{
    const int qt = blockIdx.x;
    const int h  = blockIdx.y;
    const int b  = blockIdx.z;

    const float* Qg = g_Q + (((size_t)(b * H_ + h)) * S_) * D_;
    const float* Kg = g_K + (((size_t)(b * H_ + h)) * S_) * D_;
    const float* Vg = g_V + (((size_t)(b * H_ + h)) * S_) * D_;

    extern __shared__ float sm[];
    float* Qs = sm;
    float* Ks = Qs + 128 * QS_STRIDE;
    float* Vs = Ks + 128 * QS_STRIDE;
    float* Ps = Vs + 64 * 128;

    const int tid = threadIdx.x;
    const int tx  = tid & 15;
    const int ty  = tid >> 4;

#pragma unroll
    for (int it = 0; it < 8; it++) {
        int lin = it * 256 + tid;
        int q   = lin >> 5;
        int c4  = (lin & 31) << 2;
        float4 v = *(const float4*)&Qg[(size_t)(qt * 64 + q) * D_ + c4];
        Qs[(c4 + 0) * QS_STRIDE + q] = v.x;
        Qs[(c4 + 1) * QS_STRIDE + q] = v.y;
        Qs[(c4 + 2) * QS_STRIDE + q] = v.z;
        Qs[(c4 + 3) * QS_STRIDE + q] = v.w;
    }

    float m_[4], l_[4], o_[4][8];
#pragma unroll
    for (int i = 0; i < 4; i++) {
        m_[i] = -INFINITY; l_[i] = 0.f;
#pragma unroll
        for (int j = 0; j < 8; j++) o_[i][j] = 0.f;
    }
    const float scale = 0.088388347648318447f;

    for (int kt = 0; kt <= qt; kt++) {
        __syncthreads();
#pragma unroll
        for (int it = 0; it < 8; it++) {
            int lin = it * 256 + tid;
            int r   = lin >> 5;
            int c4  = (lin & 31) << 2;
            float4 kv = *(const float4*)&Kg[(size_t)(kt * 64 + r) * D_ + c4];
            Ks[(c4 + 0) * QS_STRIDE + r] = kv.x;
            Ks[(c4 + 1) * QS_STRIDE + r] = kv.y;
            Ks[(c4 + 2) * QS_STRIDE + r] = kv.z;
            Ks[(c4 + 3) * QS_STRIDE + r] = kv.w;
            float4 vv = *(const float4*)&Vg[(size_t)(kt * 64 + r) * D_ + c4];
            *(float4*)&Vs[r * 128 + c4] = vv;
        }
        __syncthreads();

        float s4[4][4] = {};
#pragma unroll 8
        for (int d = 0; d < 128; d++) {
            float4 ra = *(const float4*)&Qs[d * QS_STRIDE + (ty << 2)];
            float4 rb = *(const float4*)&Ks[d * QS_STRIDE + (tx << 2)];
            float av[4] = {ra.x, ra.y, ra.z, ra.w};
            float bv[4] = {rb.x, rb.y, rb.z, rb.w};
#pragma unroll
            for (int i = 0; i < 4; i++)
#pragma unroll
                for (int j = 0; j < 4; j++)
                    s4[i][j] = fmaf(av[i], bv[j], s4[i][j]);
        }

        const bool diag = (kt == qt);
#pragma unroll
        for (int i = 0; i < 4; i++) {
            int qq = (ty << 2) + i;
#pragma unroll
            for (int j = 0; j < 4; j++) {
                s4[i][j] *= scale;
                if (diag && ((tx << 2) + j) > qq) s4[i][j] = -INFINITY;
            }
        }

#pragma unroll
        for (int i = 0; i < 4; i++) {
            float mx = fmaxf(fmaxf(s4[i][0], s4[i][1]), fmaxf(s4[i][2], s4[i][3]));
#pragma unroll
            for (int off = 1; off < 16; off <<= 1)
                mx = fmaxf(mx, __shfl_xor_sync(0xffffffffu, mx, off));
            float mn = fmaxf(m_[i], mx);
            float corr = expf(m_[i] - mn);
            m_[i] = mn;
            float rs = 0.f;
#pragma unroll
            for (int j = 0; j < 4; j++) {
                float p = expf(s4[i][j] - mn);
                s4[i][j] = p;
                rs += p;
            }
#pragma unroll
            for (int off = 1; off < 16; off <<= 1)
                rs += __shfl_xor_sync(0xffffffffu, rs, off);
            l_[i] = l_[i] * corr + rs;
#pragma unroll
            for (int jd = 0; jd < 8; jd++) o_[i][jd] *= corr;
#pragma unroll
            for (int j = 0; j < 4; j++)
                Ps[((tx << 2) + j) * QS_STRIDE + (ty << 2) + i] = s4[i][j];
        }
        __syncthreads();

#pragma unroll 4
        for (int kk = 0; kk < 64; kk++) {
            float4 p4 = *(const float4*)&Ps[kk * QS_STRIDE + (ty << 2)];
            float4 v0 = *(const float4*)&Vs[kk * 128 + (tx << 3)];
            float4 v1 = *(const float4*)&Vs[kk * 128 + (tx << 3) + 4];
            float pv[4] = {p4.x, p4.y, p4.z, p4.w};
            float vv[8] = {v0.x, v0.y, v0.z, v0.w, v1.x, v1.y, v1.z, v1.w};
#pragma unroll
            for (int i = 0; i < 4; i++)
#pragma unroll
                for (int jd = 0; jd < 8; jd++)
                    o_[i][jd] = fmaf(pv[i], vv[jd], o_[i][jd]);
        }
    }

#pragma unroll
    for (int i = 0; i < 4; i++) {
        float invl = 1.f / l_[i];
        int q = qt * 64 + (ty << 2) + i;
        float* dst = g_A + ((size_t)(b * S_ + q)) * E_ + h * D_ + (tx << 3);
        float4 out0 = make_float4(o_[i][0] * invl, o_[i][1] * invl,
                                  o_[i][2] * invl, o_[i][3] * invl);
        float4 out1 = make_float4(o_[i][4] * invl, o_[i][5] * invl,
                                  o_[i][6] * invl, o_[i][7] * invl);
        *(float4*)dst       = out0;
        *(float4*)(dst + 4) = out1;
    }
}

// ---------------------------------------------------------------------------
extern "C" void kernel_launch(void* const* d_in, const int* in_sizes, int n_in,
                              void* d_out, int out_size)
{
    const float* hidden = (const float*)d_in[0];
    const int*   posids = (const int*)d_in[2];
    const float* Wq     = (const float*)d_in[3];
    const float* Wk     = (const float*)d_in[4];
    const float* Wv     = (const float*)d_in[5];
    const float* Wo     = (const float*)d_in[6];
    float*       out    = (float*)d_out;

    cudaFuncSetAttribute(gemm_mma<0>,
                         cudaFuncAttributeMaxDynamicSharedMemorySize, GEMM_SMEM);
    cudaFuncSetAttribute(gemm_mma<1>,
                         cudaFuncAttributeMaxDynamicSharedMemorySize, GEMM_SMEM);
    cudaFuncSetAttribute(attn_kernel,
                         cudaFuncAttributeMaxDynamicSharedMemorySize, ATTN_SMEM_BYTES);

    // resolve device-global addresses for split targets
    __nv_bfloat16 *pXh, *pXl, *pWh, *pWl, *pAh, *pAl;
    cudaGetSymbolAddress((void**)&pXh, g_Xh);
    cudaGetSymbolAddress((void**)&pXl, g_Xl);
    cudaGetSymbolAddress((void**)&pWh, g_Wh);
    cudaGetSymbolAddress((void**)&pWl, g_Wl);
    cudaGetSymbolAddress((void**)&pAh, g_Ah);
    cudaGetSymbolAddress((void**)&pAl, g_Al);
    float* pA;
    cudaGetSymbolAddress((void**)&pA, g_A);

    const int nX4 = M_ * E_ / 4;         // 2,097,152
    const int nW4 = E_ * E_ / 4;         // 1,048,576
    const int thr = 256;

    // 1) splits of X and all weights
    split_kernel<<<nX4 / thr, thr>>>(hidden, pXh, pXl, nX4);
    split_kernel<<<nW4 / thr, thr>>>(Wq, pWh + 0 * (size_t)E_ * E_, pWl + 0 * (size_t)E_ * E_, nW4);
    split_kernel<<<nW4 / thr, thr>>>(Wk, pWh + 1 * (size_t)E_ * E_, pWl + 1 * (size_t)E_ * E_, nW4);
    split_kernel<<<nW4 / thr, thr>>>(Wv, pWh + 2 * (size_t)E_ * E_, pWl + 2 * (size_t)E_ * E_, nW4);
    split_kernel<<<nW4 / thr, thr>>>(Wo, pWh + 3 * (size_t)E_ * E_, pWl + 3 * (size_t)E_ * E_, nW4);

    // 2) QKV projections (tensor core) -> g_Q/g_K/g_V [B,H,S,D]
    {
        dim3 grid(E_ / 128, M_ / 128, 3);
        gemm_mma<0><<<grid, 256, GEMM_SMEM>>>(nullptr);
    }
    // 3) RoPE in place
    {
        dim3 grid(S_, H_, B_);
        rope_kernel<<<grid, 128>>>(posids);
    }
    // 4) causal flash attention -> g_A
    {
        dim3 grid(S_ / 64, H_, B_);
        attn_kernel<<<grid, 256, ATTN_SMEM_BYTES>>>();
    }
    // 5) split A, then output projection (tensor core) -> d_out
    split_kernel<<<nX4 / thr, thr>>>(pA, pAh, pAl, nX4);
    {
        dim3 grid(E_ / 128, M_ / 128);
        gemm_mma<1><<<grid, 256, GEMM_SMEM>>>(out);
    }
}

// round 4
// speedup vs baseline: 3.5209x; 1.6975x over previous
#include <cuda_runtime.h>
#include <cuda_bf16.h>
#include <math.h>
#include <float.h>
#include <stdint.h>

// Problem dims
#define B_ 2
#define S_ 2048
#define H_ 16
#define D_ 128
#define E_ 2048
#define M_ (B_*S_)   // 4096 tokens

// Scratch (device globals: allocation-free, graph-capturable)
__device__ float g_Q[B_*H_*S_*D_];   // fp32 QKV (GEMM outputs, pre-RoPE)
__device__ float g_K[B_*H_*S_*D_];
__device__ float g_V[B_*H_*S_*D_];

// bf16 hi/lo splits
__device__ __nv_bfloat16 g_Xh[M_*E_];
__device__ __nv_bfloat16 g_Xl[M_*E_];
__device__ __nv_bfloat16 g_Wh[4*E_*E_];     // (q,k,v,o)
__device__ __nv_bfloat16 g_Wl[4*E_*E_];
__device__ __nv_bfloat16 g_Ah[M_*E_];       // attention output split [B,S,E]
__device__ __nv_bfloat16 g_Al[M_*E_];
// post-RoPE, pre-scaled, split QKV in [B,H,S,D]
__device__ __nv_bfloat16 g_Qh[B_*H_*S_*D_];
__device__ __nv_bfloat16 g_Ql[B_*H_*S_*D_];
__device__ __nv_bfloat16 g_Kh[B_*H_*S_*D_];
__device__ __nv_bfloat16 g_Kl[B_*H_*S_*D_];
__device__ __nv_bfloat16 g_Vh[B_*H_*S_*D_];
__device__ __nv_bfloat16 g_Vl[B_*H_*S_*D_];

__device__ __forceinline__ uint32_t smem_to_u32(const void* smem_ptr) {
    uint32_t addr;
    asm("{ .reg .u64 tmp; cvta.to.shared.u64 tmp, %1; cvt.u32.u64 %0, tmp; }"
        : "=r"(addr) : "l"(smem_ptr));
    return addr;
}

#define CP_ASYNC16(dst, src) \
    asm volatile("cp.async.cg.shared.global [%0], [%1], 16;" \
        :: "r"(dst), "l"(src) : "memory")
#define CP_ASYNC_COMMIT() asm volatile("cp.async.commit_group;" ::: "memory")
#define CP_ASYNC_WAIT0()  asm volatile("cp.async.wait_group 0;" ::: "memory")

__device__ __forceinline__ void ldsm_x4(uint32_t* r, uint32_t addr) {
    asm volatile("ldmatrix.sync.aligned.m8n8.x4.shared.b16 {%0,%1,%2,%3}, [%4];"
        : "=r"(r[0]), "=r"(r[1]), "=r"(r[2]), "=r"(r[3]) : "r"(addr));
}
__device__ __forceinline__ void ldsm_x4_trans(uint32_t* r, uint32_t addr) {
    asm volatile("ldmatrix.sync.aligned.m8n8.x4.trans.shared.b16 {%0,%1,%2,%3}, [%4];"
        : "=r"(r[0]), "=r"(r[1]), "=r"(r[2]), "=r"(r[3]) : "r"(addr));
}

__device__ __forceinline__ void mma16816(float* c, const uint32_t* a,
                                          uint32_t b0, uint32_t b1) {
    asm volatile(
        "mma.sync.aligned.m16n8k16.row.col.f32.bf16.bf16.f32 "
        "{%0,%1,%2,%3}, {%4,%5,%6,%7}, {%8,%9}, {%0,%1,%2,%3};"
        : "+f"(c[0]), "+f"(c[1]), "+f"(c[2]), "+f"(c[3])
        : "r"(a[0]), "r"(a[1]), "r"(a[2]), "r"(a[3]), "r"(b0), "r"(b1));
}

__device__ __forceinline__ uint32_t pack_bf16(float lo_elem, float hi_elem) {
    __nv_bfloat162 p = __halves2bfloat162(__float2bfloat16(lo_elem),
                                          __float2bfloat16(hi_elem));
    return *(uint32_t*)&p;
}

// ---------------------------------------------------------------------------
// Split fp32 -> bf16 hi + bf16 lo
// ---------------------------------------------------------------------------
__global__ __launch_bounds__(256) void split_kernel(
    const float* __restrict__ src,
    __nv_bfloat16* __restrict__ hi,
    __nv_bfloat16* __restrict__ lo,
    int n4)
{
    int idx = blockIdx.x * blockDim.x + threadIdx.x;
    if (idx >= n4) return;
    float4 v = ((const float4*)src)[idx];
    __nv_bfloat16 h0 = __float2bfloat16(v.x);
    __nv_bfloat16 h1 = __float2bfloat16(v.y);
    __nv_bfloat16 h2 = __float2bfloat16(v.z);
    __nv_bfloat16 h3 = __float2bfloat16(v.w);
    __nv_bfloat16 l0 = __float2bfloat16(v.x - __bfloat162float(h0));
    __nv_bfloat16 l1 = __float2bfloat16(v.y - __bfloat162float(h1));
    __nv_bfloat16 l2 = __float2bfloat16(v.z - __bfloat162float(h2));
    __nv_bfloat16 l3 = __float2bfloat16(v.w - __bfloat162float(h3));
    __nv_bfloat162 hp0 = __halves2bfloat162(h0, h1);
    __nv_bfloat162 hp1 = __halves2bfloat162(h2, h3);
    __nv_bfloat162 lp0 = __halves2bfloat162(l0, l1);
    __nv_bfloat162 lp1 = __halves2bfloat162(l2, l3);
    uint2 hw, lw;
    hw.x = *(uint32_t*)&hp0; hw.y = *(uint32_t*)&hp1;
    lw.x = *(uint32_t*)&lp0; lw.y = *(uint32_t*)&lp1;
    ((uint2*)hi)[idx] = hw;
    ((uint2*)lo)[idx] = lw;
}

// ---------------------------------------------------------------------------
// RoPE + scale + split: fp32 g_Q/g_K/g_V -> bf16 hi/lo (Q scaled by 1/sqrt(D))
// block=(s,h,b), 128 threads (=D). No write hazard (dst != src arrays).
// ---------------------------------------------------------------------------
__global__ void rope_split_kernel(const int* __restrict__ pos_ids)
{
    const int d = threadIdx.x;
    const int s = blockIdx.x;
    const int h = blockIdx.y;
    const int b = blockIdx.z;

    const size_t base = (((size_t)(b * H_ + h)) * S_ + s) * D_ + d;
    const float pos = (float)pos_ids[b * S_ + s];
    const int i = d & 63;
    const float inv = powf(10000.0f, -(float)(2 * i) / (float)D_);
    float sn, cs;
    sincosf(pos * inv, &sn, &cs);
    const float scale = 0.088388347648318447f;  // 1/sqrt(128)

    float q  = g_Q[base];
    float qr = (d < 64) ? -g_Q[base + 64] : g_Q[base - 64];
    float k  = g_K[base];
    float kr = (d < 64) ? -g_K[base + 64] : g_K[base - 64];
    float v  = g_V[base];

    float qo = (q * cs + qr * sn) * scale;
    float ko = (k * cs + kr * sn);

    __nv_bfloat16 qh = __float2bfloat16(qo);
    __nv_bfloat16 kh = __float2bfloat16(ko);
    __nv_bfloat16 vh = __float2bfloat16(v);
    g_Qh[base] = qh; g_Ql[base] = __float2bfloat16(qo - __bfloat162float(qh));
    g_Kh[base] = kh; g_Kl[base] = __float2bfloat16(ko - __bfloat162float(kh));
    g_Vh[base] = vh; g_Vl[base] = __float2bfloat16(v  - __bfloat162float(vh));
}

// ---------------------------------------------------------------------------
// mma.sync bf16 (3-term split) GEMM: C[m,n] = sum_k A[m,k] * W[n,k]
// Block tile 128x128, 8 warps (warp tile 32x64), K-chunk 32, double-buffered.
// MODE 0: qkv (z selects W slot 0..2, writes g_Q/g_K/g_V in [B,H,S,D])
// MODE 1: oproj (A = g_Ah/g_Al, W slot 3, writes Oout [M][E])
// ---------------------------------------------------------------------------
#define KCH 32
#define NKC (E_/KCH)          // 64
#define ROWB 80               // bytes per smem row (32 bf16 + pad 8)
#define TILE_B (128*ROWB)     // 10240
#define STG_B  (4*TILE_B)     // 40960
#define GEMM_SMEM (2*STG_B)   // 81920

template<int MODE>
__global__ __launch_bounds__(256, 1) void gemm_mma(float* __restrict__ Oout)
{
    extern __shared__ char gsm[];
    const uint32_t sb = smem_to_u32(gsm);

    const int tid  = threadIdx.x;
    const int lane = tid & 31;
    const int wid  = tid >> 5;
    const int warpM = wid & 3;
    const int warpN = wid >> 2;
    const int m0 = blockIdx.y * 128;
    const int n0 = blockIdx.x * 128;
    const int z  = (MODE == 0) ? blockIdx.z : 3;

    const __nv_bfloat16* Ahg = (MODE == 0) ? g_Xh : g_Ah;
    const __nv_bfloat16* Alg = (MODE == 0) ? g_Xl : g_Al;
    const __nv_bfloat16* Bhg = g_Wh + (size_t)z * E_ * E_;
    const __nv_bfloat16* Blg = g_Wl + (size_t)z * E_ * E_;

    const int r0c = tid >> 2, p0 = tid & 3;
    const int r1c = r0c + 64, p1 = p0;

    float c[2][8][4];
#pragma unroll
    for (int i = 0; i < 2; i++)
#pragma unroll
        for (int j = 0; j < 8; j++)
#pragma unroll
            for (int q = 0; q < 4; q++) c[i][j][q] = 0.f;

    const uint32_t aRow = (uint32_t)(warpM * 32 + (lane & 15)) * ROWB + (uint32_t)(lane >> 4) * 16;
    const uint32_t bRow = (uint32_t)(warpN * 64 + (lane & 7) + ((lane >> 4) << 3)) * ROWB
                        + (uint32_t)((lane >> 3) & 1) * 16;

    auto load_stage = [&](int buf, int kc) {
        const uint32_t stg = sb + buf * STG_B;
        const size_t gA0 = (size_t)(m0 + r0c) * E_ + kc * KCH + p0 * 8;
        const size_t gA1 = (size_t)(m0 + r1c) * E_ + kc * KCH + p1 * 8;
        const size_t gB0 = (size_t)(n0 + r0c) * E_ + kc * KCH + p0 * 8;
        const size_t gB1 = (size_t)(n0 + r1c) * E_ + kc * KCH + p1 * 8;
        const uint32_t s0 = (uint32_t)(r0c * ROWB + p0 * 16);
        const uint32_t s1 = (uint32_t)(r1c * ROWB + p1 * 16);
        CP_ASYNC16(stg + 0 * TILE_B + s0, Ahg + gA0);
        CP_ASYNC16(stg + 0 * TILE_B + s1, Ahg + gA1);
        CP_ASYNC16(stg + 1 * TILE_B + s0, Alg + gA0);
        CP_ASYNC16(stg + 1 * TILE_B + s1, Alg + gA1);
        CP_ASYNC16(stg + 2 * TILE_B + s0, Bhg + gB0);
        CP_ASYNC16(stg + 2 * TILE_B + s1, Bhg + gB1);
        CP_ASYNC16(stg + 3 * TILE_B + s0, Blg + gB0);
        CP_ASYNC16(stg + 3 * TILE_B + s1, Blg + gB1);
        CP_ASYNC_COMMIT();
    };

    load_stage(0, 0);

    for (int kc = 0; kc < NKC; kc++) {
        const int buf = kc & 1;
        CP_ASYNC_WAIT0();
        __syncthreads();
        if (kc + 1 < NKC) load_stage(buf ^ 1, kc + 1);

        const uint32_t stg = sb + buf * STG_B;
#pragma unroll
        for (int ks = 0; ks < 2; ks++) {
            uint32_t ah[2][4], al[2][4], bh[4][4], bl[4][4];
#pragma unroll
            for (int mi = 0; mi < 2; mi++) {
                uint32_t aoff = stg + aRow + (uint32_t)mi * 16 * ROWB + (uint32_t)ks * 32;
                ldsm_x4(ah[mi], aoff + 0 * TILE_B);
                ldsm_x4(al[mi], aoff + 1 * TILE_B);
            }
#pragma unroll
            for (int g = 0; g < 4; g++) {
                uint32_t boff = stg + bRow + (uint32_t)g * 16 * ROWB + (uint32_t)ks * 32;
                ldsm_x4(bh[g], boff + 2 * TILE_B);
                ldsm_x4(bl[g], boff + 3 * TILE_B);
            }
#pragma unroll
            for (int mi = 0; mi < 2; mi++) {
#pragma unroll
                for (int g = 0; g < 4; g++) {
#pragma unroll
                    for (int hh = 0; hh < 2; hh++) {
                        float* cc = c[mi][2 * g + hh];
                        mma16816(cc, ah[mi], bh[g][2 * hh], bh[g][2 * hh + 1]);
                        mma16816(cc, ah[mi], bl[g][2 * hh], bl[g][2 * hh + 1]);
                        mma16816(cc, al[mi], bh[g][2 * hh], bh[g][2 * hh + 1]);
                    }
                }
            }
        }
        __syncthreads();
    }

    const int rr = lane >> 2;
    const int ct = 2 * (lane & 3);
#pragma unroll
    for (int mi = 0; mi < 2; mi++) {
#pragma unroll
        for (int ni = 0; ni < 8; ni++) {
            int row = m0 + warpM * 32 + mi * 16 + rr;
            int col = n0 + warpN * 64 + ni * 8 + ct;
            if (MODE == 0) {
                float* Out = (z == 0) ? g_Q : (z == 1) ? g_K : g_V;
                const int h = col >> 7;
                const int d = col & 127;
                int bb = row >> 11, ss = row & (S_ - 1);
                size_t base0 = (((size_t)(bb * H_ + h)) * S_ + ss) * D_ + d;
                *(float2*)&Out[base0] = make_float2(c[mi][ni][0], c[mi][ni][1]);
                int row2 = row + 8;
                bb = row2 >> 11; ss = row2 & (S_ - 1);
                size_t base1 = (((size_t)(bb * H_ + h)) * S_ + ss) * D_ + d;
                *(float2*)&Out[base1] = make_float2(c[mi][ni][2], c[mi][ni][3]);
            } else {
                *(float2*)&Oout[(size_t)row * E_ + col] =
                    make_float2(c[mi][ni][0], c[mi][ni][1]);
                *(float2*)&Oout[(size_t)(row + 8) * E_ + col] =
                    make_float2(c[mi][ni][2], c[mi][ni][3]);
            }
        }
    }
}

// ---------------------------------------------------------------------------
// Causal flash attention on tensor cores (bf16 hi/lo split mma).
// block = (qt, h, b); 4 warps (128 threads). BQ=64, BK=64, D=128.
// Each warp owns 16 query rows. Epilogue writes hi/lo split of A.
// ---------------------------------------------------------------------------
#define AROW 272                 // 128 bf16 = 256B + 16B pad
#define ATILE (64*AROW)          // 17408
#define A_KH 0
#define A_KL (1*ATILE)
#define A_VH (2*ATILE)
#define A_VL (3*ATILE)
#define A_QH (4*ATILE)
#define A_QL (5*ATILE)
#define ATTN_SMEM (6*ATILE)      // 104448

__global__ __launch_bounds__(128, 1) void attn_mma()
{
    const int qt = blockIdx.x;
    const int h  = blockIdx.y;
    const int b  = blockIdx.z;

    extern __shared__ char asm_[];
    const uint32_t sb = smem_to_u32(asm_);

    const int tid  = threadIdx.x;
    const int lane = tid & 31;
    const int warp = tid >> 5;

    const size_t headoff = (((size_t)(b * H_ + h)) * S_) * D_;
    const __nv_bfloat16* Qh = g_Qh + headoff;
    const __nv_bfloat16* Ql = g_Ql + headoff;
    const __nv_bfloat16* Kh = g_Kh + headoff;
    const __nv_bfloat16* Kl = g_Kl + headoff;
    const __nv_bfloat16* Vh = g_Vh + headoff;
    const __nv_bfloat16* Vl = g_Vl + headoff;

    // --- load Q tiles (hi/lo) into smem, 64x128 each ---
    {
#pragma unroll
        for (int it = 0; it < 8; it++) {
            int lin = it * 128 + tid;           // 0..1023
            int row = lin >> 4;                 // 0..63
            int c8  = (lin & 15) * 8;           // d, step 8
            const size_t src = (size_t)(qt * 64 + row) * D_ + c8;
            uint32_t dst = (uint32_t)(row * AROW + (lin & 15) * 16);
            CP_ASYNC16(sb + A_QH + dst, Qh + src);
            CP_ASYNC16(sb + A_QL + dst, Ql + src);
        }
        CP_ASYNC_COMMIT();
    }

    // fragment addresses
    const uint32_t aRow = (uint32_t)(warp * 16 + (lane & 15)) * AROW
                        + (uint32_t)(lane >> 4) * 16;                 // Q (A-frag)
    const uint32_t bRow = (uint32_t)((lane & 7) + ((lane >> 4) << 3)) * AROW
                        + (uint32_t)((lane >> 3) & 1) * 16;           // K (B-frag)
    const uint32_t vRow = (uint32_t)(lane & 15) * AROW
                        + (uint32_t)(lane >> 4) * 16;                 // V (trans)

    float m0r = -INFINITY, m1r = -INFINITY, l0r = 0.f, l1r = 0.f;
    float co[16][4];
#pragma unroll
    for (int j = 0; j < 16; j++)
#pragma unroll
        for (int q = 0; q < 4; q++) co[j][q] = 0.f;

    const int qrow0 = qt * 64 + warp * 16 + (lane >> 2);
    const int qrow1 = qrow0 + 8;

    for (int kt = 0; kt <= qt; kt++) {
        __syncthreads();   // previous iter's compute done before overwrite
        // --- load K/V tiles (hi/lo) ---
#pragma unroll
        for (int it = 0; it < 8; it++) {
            int lin = it * 128 + tid;
            int row = lin >> 4;
            int c8  = (lin & 15) * 8;
            const size_t src = (size_t)(kt * 64 + row) * D_ + c8;
            uint32_t dst = (uint32_t)(row * AROW + (lin & 15) * 16);
            CP_ASYNC16(sb + A_KH + dst, Kh + src);
            CP_ASYNC16(sb + A_KL + dst, Kl + src);
            CP_ASYNC16(sb + A_VH + dst, Vh + src);
            CP_ASYNC16(sb + A_VL + dst, Vl + src);
        }
        CP_ASYNC_COMMIT();
        CP_ASYNC_WAIT0();
        __syncthreads();

        // --- S = Q K^T (3-term split), S frag: 8 n-chunks of 8 keys ---
        float s[8][4];
#pragma unroll
        for (int j = 0; j < 8; j++)
#pragma unroll
            for (int q = 0; q < 4; q++) s[j][q] = 0.f;

#pragma unroll
        for (int kd = 0; kd < 8; kd++) {
            uint32_t qh_[4], ql_[4];
            ldsm_x4(qh_, sb + A_QH + aRow + kd * 32);
            ldsm_x4(ql_, sb + A_QL + aRow + kd * 32);
#pragma unroll
            for (int g = 0; g < 4; g++) {
                uint32_t kbh[4], kbl[4];
                uint32_t boff = bRow + (uint32_t)g * 16 * AROW + (uint32_t)kd * 32;
                ldsm_x4(kbh, sb + A_KH + boff);
                ldsm_x4(kbl, sb + A_KL + boff);
#pragma unroll
                for (int hh = 0; hh < 2; hh++) {
                    float* ss = s[2 * g + hh];
                    mma16816(ss, qh_, kbh[2 * hh], kbh[2 * hh + 1]);
                    mma16816(ss, qh_, kbl[2 * hh], kbl[2 * hh + 1]);
                    mma16816(ss, ql_, kbh[2 * hh], kbh[2 * hh + 1]);
                }
            }
        }

        // --- causal mask on diagonal tile ---
        if (kt == qt) {
            const int kbase = kt * 64 + 2 * (lane & 3);
#pragma unroll
            for (int j = 0; j < 8; j++) {
                int k0 = kbase + 8 * j;
                if (k0 > qrow0)     s[j][0] = -INFINITY;
                if (k0 + 1 > qrow0) s[j][1] = -INFINITY;
                if (k0 > qrow1)     s[j][2] = -INFINITY;
                if (k0 + 1 > qrow1) s[j][3] = -INFINITY;
            }
        }

        // --- online softmax (rows qrow0, qrow1 per thread; quad = lanes t) ---
        float mx0 = s[0][0], mx1 = s[0][2];
#pragma unroll
        for (int j = 0; j < 8; j++) {
            mx0 = fmaxf(mx0, fmaxf(s[j][0], s[j][1]));
            mx1 = fmaxf(mx1, fmaxf(s[j][2], s[j][3]));
        }
        mx0 = fmaxf(mx0, __shfl_xor_sync(0xffffffffu, mx0, 1));
        mx0 = fmaxf(mx0, __shfl_xor_sync(0xffffffffu, mx0, 2));
        mx1 = fmaxf(mx1, __shfl_xor_sync(0xffffffffu, mx1, 1));
        mx1 = fmaxf(mx1, __shfl_xor_sync(0xffffffffu, mx1, 2));

        float mn0 = fmaxf(m0r, mx0), mn1 = fmaxf(m1r, mx1);
        float corr0 = __expf(m0r - mn0), corr1 = __expf(m1r - mn1);
        m0r = mn0; m1r = mn1;

        float rs0 = 0.f, rs1 = 0.f;
#pragma unroll
        for (int j = 0; j < 8; j++) {
            s[j][0] = __expf(s[j][0] - mn0);
            s[j][1] = __expf(s[j][1] - mn0);
            s[j][2] = __expf(s[j][2] - mn1);
            s[j][3] = __expf(s[j][3] - mn1);
            rs0 += s[j][0] + s[j][1];
            rs1 += s[j][2] + s[j][3];
        }
        rs0 += __shfl_xor_sync(0xffffffffu, rs0, 1);
        rs0 += __shfl_xor_sync(0xffffffffu, rs0, 2);
        rs1 += __shfl_xor_sync(0xffffffffu, rs1, 1);
        rs1 += __shfl_xor_sync(0xffffffffu, rs1, 2);
        l0r = l0r * corr0 + rs0;
        l1r = l1r * corr1 + rs1;

#pragma unroll
        for (int j = 0; j < 16; j++) {
            co[j][0] *= corr0; co[j][1] *= corr0;
            co[j][2] *= corr1; co[j][3] *= corr1;
        }

        // --- O += P V (3-term split: Ph*Vh + Ph*Vl + Pl*Vh) ---
#pragma unroll
        for (int ks = 0; ks < 4; ks++) {
            // build P fragments from s chunks 2ks, 2ks+1
            float* cA = s[2 * ks];
            float* cB = s[2 * ks + 1];
            uint32_t ph[4], pl[4];
            {
                float hA0, hA1, hA2, hA3, hB0, hB1, hB2, hB3;
                hA0 = __bfloat162float(__float2bfloat16(cA[0]));
                hA1 = __bfloat162float(__float2bfloat16(cA[1]));
                hA2 = __bfloat162float(__float2bfloat16(cA[2]));
                hA3 = __bfloat162float(__float2bfloat16(cA[3]));
                hB0 = __bfloat162float(__float2bfloat16(cB[0]));
                hB1 = __bfloat162float(__float2bfloat16(cB[1]));
                hB2 = __bfloat162float(__float2bfloat16(cB[2]));
                hB3 = __bfloat162float(__float2bfloat16(cB[3]));
                ph[0] = pack_bf16(hA0, hA1);
                ph[1] = pack_bf16(hA2, hA3);
                ph[2] = pack_bf16(hB0, hB1);
                ph[3] = pack_bf16(hB2, hB3);
                pl[0] = pack_bf16(cA[0] - hA0, cA[1] - hA1);
                pl[1] = pack_bf16(cA[2] - hA2, cA[3] - hA3);
                pl[2] = pack_bf16(cB[0] - hB0, cB[1] - hB1);
                pl[3] = pack_bf16(cB[2] - hB2, cB[3] - hB3);
            }
#pragma unroll
            for (int dd = 0; dd < 8; dd++) {
                uint32_t vh_[4], vl_[4];
                uint32_t voff = vRow + (uint32_t)ks * 16 * AROW + (uint32_t)dd * 32;
                ldsm_x4_trans(vh_, sb + A_VH + voff);
                ldsm_x4_trans(vl_, sb + A_VL + voff);
                float* c0 = co[2 * dd];
                float* c1 = co[2 * dd + 1];
                mma16816(c0, ph, vh_[0], vh_[1]);
                mma16816(c0, ph, vl_[0], vl_[1]);
                mma16816(c0, pl, vh_[0], vh_[1]);
                mma16816(c1, ph, vh_[2], vh_[3]);
                mma16816(c1, ph, vl_[2], vl_[3]);
                mma16816(c1, pl, vh_[2], vh_[3]);
            }
        }
    }

    // --- epilogue: normalize, split hi/lo, write A in [B,S,E] ---
    const float invl0 = 1.f / l0r;
    const float invl1 = 1.f / l1r;
    const int t2 = 2 * (lane & 3);
    const size_t rowA0 = ((size_t)(b * S_ + qrow0)) * E_ + h * D_;
    const size_t rowA1 = ((size_t)(b * S_ + qrow1)) * E_ + h * D_;
#pragma unroll
    for (int j = 0; j < 16; j++) {
        int col = 8 * j + t2;
        float a0 = co[j][0] * invl0, a1 = co[j][1] * invl0;
        float a2 = co[j][2] * invl1, a3 = co[j][3] * invl1;
        float h0 = __bfloat162float(__float2bfloat16(a0));
        float h1 = __bfloat162float(__float2bfloat16(a1));
        float h2 = __bfloat162float(__float2bfloat16(a2));
        float h3 = __bfloat162float(__float2bfloat16(a3));
        *(uint32_t*)&g_Ah[rowA0 + col] = pack_bf16(h0, h1);
        *(uint32_t*)&g_Al[rowA0 + col] = pack_bf16(a0 - h0, a1 - h1);
        *(uint32_t*)&g_Ah[rowA1 + col] = pack_bf16(h2, h3);
        *(uint32_t*)&g_Al[rowA1 + col] = pack_bf16(a2 - h2, a3 - h3);
    }
}

// ---------------------------------------------------------------------------
extern "C" void kernel_launch(void* const* d_in, const int* in_sizes, int n_in,
                              void* d_out, int out_size)
{
    const float* hidden = (const float*)d_in[0];
    const int*   posids = (const int*)d_in[2];
    const float* Wq     = (const float*)d_in[3];
    const float* Wk     = (const float*)d_in[4];
    const float* Wv     = (const float*)d_in[5];
    const float* Wo     = (const float*)d_in[6];
    float*       out    = (float*)d_out;

    cudaFuncSetAttribute(gemm_mma<0>,
                         cudaFuncAttributeMaxDynamicSharedMemorySize, GEMM_SMEM);
    cudaFuncSetAttribute(gemm_mma<1>,
                         cudaFuncAttributeMaxDynamicSharedMemorySize, GEMM_SMEM);
    cudaFuncSetAttribute(attn_mma,
                         cudaFuncAttributeMaxDynamicSharedMemorySize, ATTN_SMEM);

    __nv_bfloat16 *pXh, *pXl, *pWh, *pWl;
    cudaGetSymbolAddress((void**)&pXh, g_Xh);
    cudaGetSymbolAddress((void**)&pXl, g_Xl);
    cudaGetSymbolAddress((void**)&pWh, g_Wh);
    cudaGetSymbolAddress((void**)&pWl, g_Wl);

    const int nX4 = M_ * E_ / 4;
    const int nW4 = E_ * E_ / 4;
    const int thr = 256;

    // 1) splits of X and all weights
    split_kernel<<<nX4 / thr, thr>>>(hidden, pXh, pXl, nX4);
    split_kernel<<<nW4 / thr, thr>>>(Wq, pWh + 0 * (size_t)E_ * E_, pWl + 0 * (size_t)E_ * E_, nW4);
    split_kernel<<<nW4 / thr, thr>>>(Wk, pWh + 1 * (size_t)E_ * E_, pWl + 1 * (size_t)E_ * E_, nW4);
    split_kernel<<<nW4 / thr, thr>>>(Wv, pWh + 2 * (size_t)E_ * E_, pWl + 2 * (size_t)E_ * E_, nW4);
    split_kernel<<<nW4 / thr, thr>>>(Wo, pWh + 3 * (size_t)E_ * E_, pWl + 3 * (size_t)E_ * E_, nW4);

    // 2) QKV projections (tensor core) -> fp32 g_Q/g_K/g_V [B,H,S,D]
    {
        dim3 grid(E_ / 128, M_ / 128, 3);
        gemm_mma<0><<<grid, 256, GEMM_SMEM>>>(nullptr);
    }
    // 3) RoPE + scale + bf16 split
    {
        dim3 grid(S_, H_, B_);
        rope_split_kernel<<<grid, 128>>>(posids);
    }
    // 4) causal flash attention (tensor core) -> g_Ah/g_Al
    {
        dim3 grid(S_ / 64, H_, B_);
        attn_mma<<<grid, 128, ATTN_SMEM>>>();
    }
    // 5) output projection (tensor core) -> d_out
    {
        dim3 grid(E_ / 128, M_ / 128);
        gemm_mma<1><<<grid, 256, GEMM_SMEM>>>(out);
    }
}